// round 1
// baseline (speedup 1.0000x reference)
#include <cuda_runtime.h>

// ---------------------------------------------------------------------------
// DeformableBottleneck: B=16, Cin=O=1024, H=W=32, P=256
// Stages:
//  1. bnprep: fold BN params into (scale, shift)
//  2. pack_offw / pack_w2: weight repacks for coalesced access
//  3. gemm_conv1 (TN): h = relu(bn1(x @ w1^T))  -> NHWC  g_h
//  4. offconv: offsets = 3x3 conv(h, off_w) + off_b      g_off
//  5. sampler: bilinear gather -> S[16384, 9*256]        g_S
//  6. gemm_deform (NT): h2 = relu(bn2(S @ w2t^T))        g_h2
//  7. gemm_final (NT): out = relu(bn3(h2 @ w3^T) + x)    d_out (NCHW)
// All GEMMs: 128x128x8 tiles, 256 thr, 8x8 microtile, fma.rn.f32x2 inner loop.
// ---------------------------------------------------------------------------

#define HW 1024
#define CIN 1024
#define PDIM 256
#define ODIM 1024
#define BATCH 16

__device__ float g_h  [BATCH * HW * PDIM];        // NHWC h1 (16.7 MB)
__device__ float g_h2 [BATCH * HW * PDIM];        // NHWC h2
__device__ float g_off[BATCH * 18 * HW];          // NCHW offsets
__device__ float g_S  [BATCH * HW * 9 * PDIM];    // sampled im2col (151 MB)
__device__ float g_w2t[PDIM * 9 * PDIM];          // [o][k*256+c]
__device__ float g_offw[9 * 18 * PDIM];           // [tap][j][c]
__device__ float g_s1[PDIM], g_t1[PDIM];
__device__ float g_s2[PDIM], g_t2[PDIM];
__device__ float g_s3[ODIM], g_t3[ODIM];

// ---------------- packed f32x2 helpers (FFMA2) ----------------
__device__ __forceinline__ unsigned long long pack2(float lo, float hi) {
    unsigned long long r;
    asm("mov.b64 %0, {%1, %2};" : "=l"(r) : "f"(lo), "f"(hi));
    return r;
}
__device__ __forceinline__ unsigned long long dup2(float v) {
    unsigned long long r;
    asm("mov.b64 %0, {%1, %1};" : "=l"(r) : "f"(v));
    return r;
}
__device__ __forceinline__ void unpack2(unsigned long long p, float& lo, float& hi) {
    asm("mov.b64 {%0, %1}, %2;" : "=f"(lo), "=f"(hi) : "l"(p));
}
__device__ __forceinline__ void fma2(unsigned long long& d, unsigned long long a,
                                     unsigned long long b) {
    asm("fma.rn.f32x2 %0, %1, %2, %0;" : "+l"(d) : "l"(a), "l"(b));
}

// ---------------- stage 1: BN fold ----------------
__global__ void bnprep(const float* __restrict__ g1, const float* __restrict__ b1,
                       const float* __restrict__ m1, const float* __restrict__ v1,
                       const float* __restrict__ g2, const float* __restrict__ b2,
                       const float* __restrict__ m2, const float* __restrict__ v2,
                       const float* __restrict__ g3, const float* __restrict__ b3,
                       const float* __restrict__ m3, const float* __restrict__ v3) {
    int i = blockIdx.x * 256 + threadIdx.x;
    if (i < PDIM) {
        float s = g1[i] / sqrtf(v1[i] + 1e-5f);
        g_s1[i] = s; g_t1[i] = b1[i] - m1[i] * s;
        s = g2[i] / sqrtf(v2[i] + 1e-5f);
        g_s2[i] = s; g_t2[i] = b2[i] - m2[i] * s;
    }
    if (i < ODIM) {
        float s = g3[i] / sqrtf(v3[i] + 1e-5f);
        g_s3[i] = s; g_t3[i] = b3[i] - m3[i] * s;
    }
}

// ---------------- stage 2: weight repacks ----------------
// off_w [j][c][tap] -> g_offw [tap][j][c]
__global__ void pack_offw(const float* __restrict__ w) {
    int idx = blockIdx.x * 256 + threadIdx.x;   // < 9*18*256
    int c = idx & 255;
    int j = (idx >> 8) % 18;
    int tap = idx / (256 * 18);
    g_offw[(tap * 18 + j) * 256 + c] = w[(j * 256 + c) * 9 + tap];
}
// w2 [o][c][tap] -> g_w2t [o][tap*256+c]
__global__ void pack_w2(const float* __restrict__ w) {
    int idx = blockIdx.x * 256 + threadIdx.x;   // < 256*2304
    int o = idx / 2304;
    int r = idx % 2304;
    int k = r >> 8;
    int c = r & 255;
    g_w2t[idx] = w[(o * 256 + c) * 9 + k];
}

// ---------------- stage 3: conv1x1 + BN1 + ReLU (TN gemm) ----------------
// C[m=hw, n=p] = sum_c x_b[c][m] * w1[n][c];  grid (2, 8, 16), 256 thr
__global__ void gemm_conv1(const float* __restrict__ X, const float* __restrict__ W1) {
    __shared__ float As[8][132];
    __shared__ float Bs[8][132];
    const int b  = blockIdx.z;
    const int bn = blockIdx.x * 128;
    const int bm = blockIdx.y * 128;
    const int tid = threadIdx.x;
    const int lk = tid >> 5;            // 0..7
    const int lm = (tid & 31) << 2;     // 0..124
    const int ln = tid >> 1;            // 0..127
    const int lq = (tid & 1) << 2;      // 0 or 4
    const int ty = tid >> 4, tx = tid & 15;
    const float* A = X + b * (CIN * HW);

    unsigned long long acc2[8][4];
#pragma unroll
    for (int i = 0; i < 8; i++)
#pragma unroll
        for (int j = 0; j < 4; j++) acc2[i][j] = 0ull;

    for (int k0 = 0; k0 < CIN; k0 += 8) {
        float4 av = *(const float4*)(A + (k0 + lk) * HW + bm + lm);
        float4 bv = *(const float4*)(W1 + (bn + ln) * CIN + k0 + lq);
        __syncthreads();
        *(float4*)&As[lk][lm] = av;
        Bs[lq + 0][ln] = bv.x; Bs[lq + 1][ln] = bv.y;
        Bs[lq + 2][ln] = bv.z; Bs[lq + 3][ln] = bv.w;
        __syncthreads();
#pragma unroll
        for (int kk = 0; kk < 8; kk++) {
            float a[8], bf[8];
            *(float4*)&a[0]  = *(const float4*)&As[kk][ty * 8];
            *(float4*)&a[4]  = *(const float4*)&As[kk][ty * 8 + 4];
            *(float4*)&bf[0] = *(const float4*)&Bs[kk][tx * 8];
            *(float4*)&bf[4] = *(const float4*)&Bs[kk][tx * 8 + 4];
            unsigned long long b2[4];
#pragma unroll
            for (int j = 0; j < 4; j++) b2[j] = pack2(bf[2 * j], bf[2 * j + 1]);
#pragma unroll
            for (int i = 0; i < 8; i++) {
                unsigned long long a2 = dup2(a[i]);
#pragma unroll
                for (int j = 0; j < 4; j++) fma2(acc2[i][j], a2, b2[j]);
            }
        }
    }
    float accf[8][8];
#pragma unroll
    for (int i = 0; i < 8; i++)
#pragma unroll
        for (int j = 0; j < 4; j++)
            unpack2(acc2[i][j], accf[i][2 * j], accf[i][2 * j + 1]);

#pragma unroll
    for (int i = 0; i < 8; i++) {
        int m = bm + ty * 8 + i;
        float v[8];
#pragma unroll
        for (int j = 0; j < 8; j++) {
            int n = bn + tx * 8 + j;
            v[j] = fmaxf(fmaf(accf[i][j], g_s1[n], g_t1[n]), 0.0f);
        }
        float4* dst = (float4*)(g_h + (b * HW + m) * PDIM + bn + tx * 8);
        dst[0] = make_float4(v[0], v[1], v[2], v[3]);
        dst[1] = make_float4(v[4], v[5], v[6], v[7]);
    }
}

// ---------------- stage 4: offset conv (3x3, 256 -> 18) ----------------
// grid 512 = (b, y), block 512 = 16 warps * 32 lanes; warp handles 2 x's,
// lanes stride channels, shuffle-reduce at the end.
__global__ void offconv_kernel(const float* __restrict__ off_b) {
    __shared__ float wS[18 * 256];
    const int b = blockIdx.x >> 5;
    const int y = blockIdx.x & 31;
    const int warp = threadIdx.x >> 5;
    const int lane = threadIdx.x & 31;
    const int xa0 = warp * 2, xb0 = warp * 2 + 1;
    const float* hb = g_h + b * (HW * PDIM);

    float acc0[18], acc1[18];
#pragma unroll
    for (int j = 0; j < 18; j++) { acc0[j] = 0.0f; acc1[j] = 0.0f; }

    for (int tap = 0; tap < 9; tap++) {
        __syncthreads();
        for (int i = threadIdx.x; i < 1152; i += 512)
            ((float4*)wS)[i] = ((const float4*)(g_offw + tap * 4608))[i];
        __syncthreads();
        int yy = y + tap / 3 - 1;
        if (yy < 0 || yy > 31) continue;        // uniform per block
        int dx = tap % 3 - 1;
        int xa = xa0 + dx, xb = xb0 + dx;
        const float* rowp = hb + yy * (32 * PDIM);
#pragma unroll
        for (int half = 0; half < 2; half++) {
            int p = lane * 4 + half * 128;
            float4 ha = make_float4(0, 0, 0, 0), hbv = make_float4(0, 0, 0, 0);
            if (xa >= 0 && xa <= 31) ha  = *(const float4*)(rowp + xa * PDIM + p);
            if (xb >= 0 && xb <= 31) hbv = *(const float4*)(rowp + xb * PDIM + p);
#pragma unroll
            for (int j = 0; j < 18; j++) {
                float4 wv = *(const float4*)(wS + j * 256 + p);
                acc0[j] += ha.x * wv.x + ha.y * wv.y + ha.z * wv.z + ha.w * wv.w;
                acc1[j] += hbv.x * wv.x + hbv.y * wv.y + hbv.z * wv.z + hbv.w * wv.w;
            }
        }
    }
    for (int j = 0; j < 18; j++) {
        float r0 = acc0[j], r1 = acc1[j];
        for (int o = 16; o > 0; o >>= 1) {
            r0 += __shfl_xor_sync(0xffffffffu, r0, o);
            r1 += __shfl_xor_sync(0xffffffffu, r1, o);
        }
        if (lane == 0) {
            float bb = off_b[j];
            float* dst = g_off + ((b * 18 + j) * 32 + y) * 32;
            dst[xa0] = r0 + bb;
            dst[xb0] = r1 + bb;
        }
    }
}

// ---------------- stage 5: bilinear sampler ----------------
// item = (b, hw, k); one warp per item; lanes over channels.
__global__ void sampler_kernel() {
    int gi = blockIdx.x * 8 + (threadIdx.x >> 5);   // < 16*1024*9
    int lane = threadIdx.x & 31;
    int k = gi % 9;
    int t = gi / 9;              // b*1024 + hw
    int hw = t & 1023;
    int b = t >> 10;
    int y = hw >> 5, xx = hw & 31;

    const float* offp = g_off + b * (18 * HW) + (2 * k) * HW + hw;
    float oy = offp[0];
    float ox = offp[HW];
    float py = (float)(y + k / 3 - 1) + oy;
    float px = (float)(xx + k % 3 - 1) + ox;
    float y0f = floorf(py), x0f = floorf(px);
    float wy = py - y0f, wx = px - x0f;
    int y0 = (int)y0f, x0 = (int)x0f;
    int y1 = y0 + 1, x1 = x0 + 1;
    float vy0 = (y0 >= 0 && y0 <= 31) ? 1.0f : 0.0f;
    float vy1 = (y1 >= 0 && y1 <= 31) ? 1.0f : 0.0f;
    float vx0 = (x0 >= 0 && x0 <= 31) ? 1.0f : 0.0f;
    float vx1 = (x1 >= 0 && x1 <= 31) ? 1.0f : 0.0f;
    float w00 = (1.0f - wy) * (1.0f - wx) * vy0 * vx0;
    float w01 = (1.0f - wy) * wx * vy0 * vx1;
    float w10 = wy * (1.0f - wx) * vy1 * vx0;
    float w11 = wy * wx * vy1 * vx1;
    int y0c = min(max(y0, 0), 31), y1c = min(max(y1, 0), 31);
    int x0c = min(max(x0, 0), 31), x1c = min(max(x1, 0), 31);

    const float* base = g_h + b * (HW * PDIM);
    const float* p00 = base + (y0c * 32 + x0c) * PDIM;
    const float* p01 = base + (y0c * 32 + x1c) * PDIM;
    const float* p10 = base + (y1c * 32 + x0c) * PDIM;
    const float* p11 = base + (y1c * 32 + x1c) * PDIM;
    float* dst = g_S + (t * 9 + k) * PDIM;

#pragma unroll
    for (int half = 0; half < 2; half++) {
        int c = lane * 4 + half * 128;
        float4 a = *(const float4*)(p00 + c);
        float4 bq = *(const float4*)(p01 + c);
        float4 cq = *(const float4*)(p10 + c);
        float4 dq = *(const float4*)(p11 + c);
        float4 r;
        r.x = w00 * a.x + w01 * bq.x + w10 * cq.x + w11 * dq.x;
        r.y = w00 * a.y + w01 * bq.y + w10 * cq.y + w11 * dq.y;
        r.z = w00 * a.z + w01 * bq.z + w10 * cq.z + w11 * dq.z;
        r.w = w00 * a.w + w01 * bq.w + w10 * cq.w + w11 * dq.w;
        *(float4*)(dst + c) = r;
    }
}

// ---------------- stage 6: deform GEMM (NT) + BN2 + ReLU ----------------
// C[m, n=p] = sum_k S[m][k] * w2t[n][k], K=2304;  grid (2, 128)
__global__ void gemm_deform() {
    __shared__ float As[8][132];
    __shared__ float Bs[8][132];
    const int bn = blockIdx.x * 128;
    const int bm = blockIdx.y * 128;
    const int tid = threadIdx.x;
    const int ln = tid >> 1;
    const int lq = (tid & 1) << 2;
    const int ty = tid >> 4, tx = tid & 15;
    const int K = 9 * PDIM;

    unsigned long long acc2[8][4];
#pragma unroll
    for (int i = 0; i < 8; i++)
#pragma unroll
        for (int j = 0; j < 4; j++) acc2[i][j] = 0ull;

    for (int k0 = 0; k0 < K; k0 += 8) {
        float4 av = *(const float4*)(g_S + (bm + ln) * K + k0 + lq);
        float4 bv = *(const float4*)(g_w2t + (bn + ln) * K + k0 + lq);
        __syncthreads();
        As[lq + 0][ln] = av.x; As[lq + 1][ln] = av.y;
        As[lq + 2][ln] = av.z; As[lq + 3][ln] = av.w;
        Bs[lq + 0][ln] = bv.x; Bs[lq + 1][ln] = bv.y;
        Bs[lq + 2][ln] = bv.z; Bs[lq + 3][ln] = bv.w;
        __syncthreads();
#pragma unroll
        for (int kk = 0; kk < 8; kk++) {
            float a[8], bf[8];
            *(float4*)&a[0]  = *(const float4*)&As[kk][ty * 8];
            *(float4*)&a[4]  = *(const float4*)&As[kk][ty * 8 + 4];
            *(float4*)&bf[0] = *(const float4*)&Bs[kk][tx * 8];
            *(float4*)&bf[4] = *(const float4*)&Bs[kk][tx * 8 + 4];
            unsigned long long b2[4];
#pragma unroll
            for (int j = 0; j < 4; j++) b2[j] = pack2(bf[2 * j], bf[2 * j + 1]);
#pragma unroll
            for (int i = 0; i < 8; i++) {
                unsigned long long a2 = dup2(a[i]);
#pragma unroll
                for (int j = 0; j < 4; j++) fma2(acc2[i][j], a2, b2[j]);
            }
        }
    }
    float accf[8][8];
#pragma unroll
    for (int i = 0; i < 8; i++)
#pragma unroll
        for (int j = 0; j < 4; j++)
            unpack2(acc2[i][j], accf[i][2 * j], accf[i][2 * j + 1]);

#pragma unroll
    for (int i = 0; i < 8; i++) {
        int m = bm + ty * 8 + i;
        float v[8];
#pragma unroll
        for (int j = 0; j < 8; j++) {
            int n = bn + tx * 8 + j;
            v[j] = fmaxf(fmaf(accf[i][j], g_s2[n], g_t2[n]), 0.0f);
        }
        float4* dst = (float4*)(g_h2 + m * PDIM + bn + tx * 8);
        dst[0] = make_float4(v[0], v[1], v[2], v[3]);
        dst[1] = make_float4(v[4], v[5], v[6], v[7]);
    }
}

// ---------------- stage 7: final conv1x1 + BN3 + residual + ReLU ----------------
// C[m=hw, n=o] = sum_p h2_b[m][p] * w3[n][p];  grid (8, 8, 16)
__global__ void gemm_final(const float* __restrict__ X, const float* __restrict__ W3,
                           float* __restrict__ OUT) {
    __shared__ float As[8][132];
    __shared__ float Bs[8][132];
    const int b  = blockIdx.z;
    const int bn = blockIdx.x * 128;
    const int bm = blockIdx.y * 128;
    const int tid = threadIdx.x;
    const int ln = tid >> 1;
    const int lq = (tid & 1) << 2;
    const int ty = tid >> 4, tx = tid & 15;
    const float* A = g_h2 + b * (HW * PDIM);

    unsigned long long acc2[8][4];
#pragma unroll
    for (int i = 0; i < 8; i++)
#pragma unroll
        for (int j = 0; j < 4; j++) acc2[i][j] = 0ull;

    for (int k0 = 0; k0 < PDIM; k0 += 8) {
        float4 av = *(const float4*)(A + (bm + ln) * PDIM + k0 + lq);
        float4 bv = *(const float4*)(W3 + (bn + ln) * PDIM + k0 + lq);
        __syncthreads();
        As[lq + 0][ln] = av.x; As[lq + 1][ln] = av.y;
        As[lq + 2][ln] = av.z; As[lq + 3][ln] = av.w;
        Bs[lq + 0][ln] = bv.x; Bs[lq + 1][ln] = bv.y;
        Bs[lq + 2][ln] = bv.z; Bs[lq + 3][ln] = bv.w;
        __syncthreads();
#pragma unroll
        for (int kk = 0; kk < 8; kk++) {
            float a[8], bf[8];
            *(float4*)&a[0]  = *(const float4*)&As[kk][ty * 8];
            *(float4*)&a[4]  = *(const float4*)&As[kk][ty * 8 + 4];
            *(float4*)&bf[0] = *(const float4*)&Bs[kk][tx * 8];
            *(float4*)&bf[4] = *(const float4*)&Bs[kk][tx * 8 + 4];
            unsigned long long b2[4];
#pragma unroll
            for (int j = 0; j < 4; j++) b2[j] = pack2(bf[2 * j], bf[2 * j + 1]);
#pragma unroll
            for (int i = 0; i < 8; i++) {
                unsigned long long a2 = dup2(a[i]);
#pragma unroll
                for (int j = 0; j < 4; j++) fma2(acc2[i][j], a2, b2[j]);
            }
        }
    }
    float accf[8][8];
#pragma unroll
    for (int i = 0; i < 8; i++)
#pragma unroll
        for (int j = 0; j < 4; j++)
            unpack2(acc2[i][j], accf[i][2 * j], accf[i][2 * j + 1]);

    const float* xb = X + b * (ODIM * HW);
    float* ob = OUT + b * (ODIM * HW);
    const int m0 = bm + ty * 8;
#pragma unroll
    for (int j = 0; j < 8; j++) {
        int n = bn + tx * 8 + j;
        float s = g_s3[n], t = g_t3[n];
        const float4* xp = (const float4*)(xb + n * HW + m0);
        float4* op = (float4*)(ob + n * HW + m0);
        float4 x0 = xp[0], x1 = xp[1];
        float4 r0, r1;
        r0.x = fmaxf(fmaf(accf[0][j], s, t) + x0.x, 0.0f);
        r0.y = fmaxf(fmaf(accf[1][j], s, t) + x0.y, 0.0f);
        r0.z = fmaxf(fmaf(accf[2][j], s, t) + x0.z, 0.0f);
        r0.w = fmaxf(fmaf(accf[3][j], s, t) + x0.w, 0.0f);
        r1.x = fmaxf(fmaf(accf[4][j], s, t) + x1.x, 0.0f);
        r1.y = fmaxf(fmaf(accf[5][j], s, t) + x1.y, 0.0f);
        r1.z = fmaxf(fmaf(accf[6][j], s, t) + x1.z, 0.0f);
        r1.w = fmaxf(fmaf(accf[7][j], s, t) + x1.w, 0.0f);
        op[0] = r0;
        op[1] = r1;
    }
}

// ---------------- launcher ----------------
extern "C" void kernel_launch(void* const* d_in, const int* in_sizes, int n_in,
                              void* d_out, int out_size) {
    const float* x     = (const float*)d_in[0];
    const float* w1    = (const float*)d_in[1];
    const float* bn1g  = (const float*)d_in[2];
    const float* bn1b  = (const float*)d_in[3];
    const float* bn1m  = (const float*)d_in[4];
    const float* bn1v  = (const float*)d_in[5];
    const float* off_w = (const float*)d_in[6];
    const float* off_b = (const float*)d_in[7];
    const float* w2    = (const float*)d_in[8];
    const float* bn2g  = (const float*)d_in[9];
    const float* bn2b  = (const float*)d_in[10];
    const float* bn2m  = (const float*)d_in[11];
    const float* bn2v  = (const float*)d_in[12];
    const float* w3    = (const float*)d_in[13];
    const float* bn3g  = (const float*)d_in[14];
    const float* bn3b  = (const float*)d_in[15];
    const float* bn3m  = (const float*)d_in[16];
    const float* bn3v  = (const float*)d_in[17];
    float* out = (float*)d_out;

    bnprep<<<4, 256>>>(bn1g, bn1b, bn1m, bn1v, bn2g, bn2b, bn2m, bn2v,
                       bn3g, bn3b, bn3m, bn3v);
    pack_offw<<<162, 256>>>(off_w);
    pack_w2<<<2304, 256>>>(w2);
    gemm_conv1<<<dim3(2, 8, 16), 256>>>(x, w1);
    offconv_kernel<<<512, 512>>>(off_b);
    sampler_kernel<<<18432, 256>>>();
    gemm_deform<<<dim3(2, 128), 256>>>();
    gemm_final<<<dim3(8, 8, 16), 256>>>(x, w3, out);
}

// round 3
// speedup vs baseline: 1.1138x; 1.1138x over previous
#include <cuda_runtime.h>
#include <cuda_bf16.h>

// ---------------------------------------------------------------------------
// DeformableBottleneck: B=16, Cin=O=1024, H=W=32, P=256.
// GEMMs on tensor cores via mma.sync.m16n8k16.bf16 (sm_80+ PTX, legal at
// target sm_103), bf16x3 error compensation (Ah*Bh + Ah*Bl + Al*Bh), fp32 acc.
// CTA tile 128x128, K-tile 32, 8 warps (2m x 4n), warp tile 64x32,
// double-buffered smem (padded stride 36 bf16).
// ---------------------------------------------------------------------------

#define HW 1024
#define CIN 1024
#define PDIM 256
#define ODIM 1024
#define BATCH 16

__device__ float g_h  [BATCH * HW * PDIM];
__device__ float g_h2 [BATCH * HW * PDIM];
__device__ float g_off[BATCH * 18 * HW];
__device__ float g_S  [BATCH * HW * 9 * PDIM];
__device__ float g_w2t[PDIM * 9 * PDIM];
__device__ float g_offw[9 * 18 * PDIM];
__device__ float g_s1[PDIM], g_t1[PDIM];
__device__ float g_s2[PDIM], g_t2[PDIM];
__device__ float g_s3[ODIM], g_t3[ODIM];

// smem geometry (bf16 elems, padded row stride 36 = 72 B)
#define SROW 36
#define TILE_BYTES (128 * SROW * 2)          // 9216
#define BUF_BYTES  (4 * TILE_BYTES)          // Ah, Al, Bh, Bl = 36864
#define SMEM_TOTAL (2 * BUF_BYTES + 128)     // double buffer (+ slack)

// ------------------------- helpers -------------------------
__device__ __forceinline__ unsigned packbf(float lo, float hi) {
    unsigned r;
    asm("cvt.rn.bf16x2.f32 %0, %1, %2;" : "=r"(r) : "f"(hi), "f"(lo));
    return r;
}
__device__ __forceinline__ void mma_bf16(float* d, const unsigned* a, const unsigned* b) {
    asm volatile(
        "mma.sync.aligned.m16n8k16.row.col.f32.bf16.bf16.f32 "
        "{%0,%1,%2,%3}, {%4,%5,%6,%7}, {%8,%9}, {%0,%1,%2,%3};"
        : "+f"(d[0]), "+f"(d[1]), "+f"(d[2]), "+f"(d[3])
        : "r"(a[0]), "r"(a[1]), "r"(a[2]), "r"(a[3]), "r"(b[0]), "r"(b[1]));
}

// ------------------------- small kernels -------------------------
__global__ void bnprep(const float* __restrict__ g1, const float* __restrict__ b1,
                       const float* __restrict__ m1, const float* __restrict__ v1,
                       const float* __restrict__ g2, const float* __restrict__ b2,
                       const float* __restrict__ m2, const float* __restrict__ v2,
                       const float* __restrict__ g3, const float* __restrict__ b3,
                       const float* __restrict__ m3, const float* __restrict__ v3) {
    int i = blockIdx.x * 256 + threadIdx.x;
    if (i < PDIM) {
        float s = g1[i] / sqrtf(v1[i] + 1e-5f);
        g_s1[i] = s; g_t1[i] = b1[i] - m1[i] * s;
        s = g2[i] / sqrtf(v2[i] + 1e-5f);
        g_s2[i] = s; g_t2[i] = b2[i] - m2[i] * s;
    }
    if (i < ODIM) {
        float s = g3[i] / sqrtf(v3[i] + 1e-5f);
        g_s3[i] = s; g_t3[i] = b3[i] - m3[i] * s;
    }
}

__global__ void pack_offw(const float* __restrict__ w) {
    int idx = blockIdx.x * 256 + threadIdx.x;
    int c = idx & 255;
    int j = (idx >> 8) % 18;
    int tap = idx / (256 * 18);
    g_offw[(tap * 18 + j) * 256 + c] = w[(j * 256 + c) * 9 + tap];
}
__global__ void pack_w2(const float* __restrict__ w) {
    int idx = blockIdx.x * 256 + threadIdx.x;
    int o = idx / 2304;
    int r = idx % 2304;
    int k = r >> 8;
    int c = r & 255;
    g_w2t[idx] = w[(o * 256 + c) * 9 + k];
}

// ------------------------- tensor-core GEMM -------------------------
// MODE 1: A = x[b] (k-major [c][hw]), B = w1 -> g_h (+bn1+relu), NHWC
// MODE 2: A = g_S [m][2304], B = g_w2t      -> g_h2 (+bn2+relu)
// MODE 3: A = g_h2 [m][256], B = w3 n-tile  -> OUT NCHW (+bn3+res+relu)
template <int MODE>
__global__ void __launch_bounds__(256) tc_gemm(const float* __restrict__ Aglob,
                                               const float* __restrict__ Bglob,
                                               const float* __restrict__ Xres,
                                               float* __restrict__ Out) {
    extern __shared__ char ds[];

    constexpr int Ktot = (MODE == 1) ? 1024 : (MODE == 2) ? 2304 : 256;
    constexpr int T = Ktot / 32;

    const int tid = threadIdx.x;
    const int wid = tid >> 5;
    const int lane = tid & 31;
    const int g = lane >> 2;        // fragment group row
    const int tq = lane & 3;        // thread-in-group
    const int mw = wid & 1;         // warp m group (0,1) -> 64 rows
    const int nw = wid >> 1;        // warp n group (0..3) -> 32 cols

    // operand resolution
    const float* Abase;
    const float* Bbase;
    int lda = 0;
    int m0 = 0, b_img = 0, hw0 = 0;
    const int n0 = blockIdx.y * 128;
    if constexpr (MODE == 1) {
        b_img = blockIdx.x >> 3;
        hw0 = (blockIdx.x & 7) << 7;
        Abase = Aglob + (size_t)b_img * (CIN * HW);
        Bbase = Bglob + (size_t)n0 * Ktot;
    } else if constexpr (MODE == 2) {
        m0 = blockIdx.x * 128;
        Abase = g_S; lda = 2304;
        Bbase = g_w2t + (size_t)n0 * Ktot;
    } else {
        m0 = blockIdx.x * 128;
        Abase = g_h2; lda = 256;
        Bbase = Bglob + (size_t)n0 * Ktot;
    }

    char* bufs[2] = { ds, ds + BUF_BYTES };

    // B loader indices (rows of B tile): row = tid>>1, 16 floats at half*16
    const int br = tid >> 1;
    const int bhalf = (tid & 1) << 4;
    // A loader indices mode2/3: same shape
    // A loader mode1: kcol = tid>>3, m chunk = (tid&7)*16
    const int akc = tid >> 3;
    const int amc = (tid & 7) << 4;

    float4 ast[4], bst[4];

    auto load_stage = [&](int t) {
        int k0 = t * 32;
#pragma unroll
        for (int q = 0; q < 4; q++)
            bst[q] = *(const float4*)(Bbase + (size_t)br * Ktot + k0 + bhalf + 4 * q);
        if constexpr (MODE == 1) {
#pragma unroll
            for (int q = 0; q < 4; q++)
                ast[q] = *(const float4*)(Abase + (size_t)(k0 + akc) * HW + hw0 + amc + 4 * q);
        } else {
#pragma unroll
            for (int q = 0; q < 4; q++)
                ast[q] = *(const float4*)(Abase + (size_t)(m0 + br) * lda + k0 + bhalf + 4 * q);
        }
    };

    auto store_stage = [&](int buf) {
        char* Ah = bufs[buf];
        char* Al = bufs[buf] + TILE_BYTES;
        char* Bh = bufs[buf] + 2 * TILE_BYTES;
        char* Bl = bufs[buf] + 3 * TILE_BYTES;
        // B rowwise
#pragma unroll
        for (int q = 0; q < 4; q++) {
            float4 v = bst[q];
            unsigned hp0 = packbf(v.x, v.y);
            unsigned hp1 = packbf(v.z, v.w);
            float hx = __uint_as_float(hp0 << 16);
            float hy = __uint_as_float(hp0 & 0xffff0000u);
            float hz = __uint_as_float(hp1 << 16);
            float hw_ = __uint_as_float(hp1 & 0xffff0000u);
            unsigned lp0 = packbf(v.x - hx, v.y - hy);
            unsigned lp1 = packbf(v.z - hz, v.w - hw_);
            unsigned off = br * (SROW * 2) + (bhalf + 4 * q) * 2;
            *(unsigned*)(Bh + off) = hp0;
            *(unsigned*)(Bh + off + 4) = hp1;
            *(unsigned*)(Bl + off) = lp0;
            *(unsigned*)(Bl + off + 4) = lp1;
        }
        if constexpr (MODE == 1) {
            // transpose scatter: elements m = amc+4q+e at col akc
#pragma unroll
            for (int q = 0; q < 4; q++) {
                float v[4] = { ast[q].x, ast[q].y, ast[q].z, ast[q].w };
#pragma unroll
                for (int e = 0; e < 4; e++) {
                    int m = amc + 4 * q + e;
                    __nv_bfloat16 hb = __float2bfloat16(v[e]);
                    __nv_bfloat16 lb = __float2bfloat16(v[e] - __bfloat162float(hb));
                    unsigned off = m * (SROW * 2) + akc * 2;
                    *(unsigned short*)(Ah + off) = __bfloat16_as_ushort(hb);
                    *(unsigned short*)(Al + off) = __bfloat16_as_ushort(lb);
                }
            }
        } else {
#pragma unroll
            for (int q = 0; q < 4; q++) {
                float4 v = ast[q];
                unsigned hp0 = packbf(v.x, v.y);
                unsigned hp1 = packbf(v.z, v.w);
                float hx = __uint_as_float(hp0 << 16);
                float hy = __uint_as_float(hp0 & 0xffff0000u);
                float hz = __uint_as_float(hp1 << 16);
                float hw_ = __uint_as_float(hp1 & 0xffff0000u);
                unsigned lp0 = packbf(v.x - hx, v.y - hy);
                unsigned lp1 = packbf(v.z - hz, v.w - hw_);
                unsigned off = br * (SROW * 2) + (bhalf + 4 * q) * 2;
                *(unsigned*)(Ah + off) = hp0;
                *(unsigned*)(Ah + off + 4) = hp1;
                *(unsigned*)(Al + off) = lp0;
                *(unsigned*)(Al + off + 4) = lp1;
            }
        }
    };

    float acc[4][4][4];
#pragma unroll
    for (int i = 0; i < 4; i++)
#pragma unroll
        for (int j = 0; j < 4; j++)
#pragma unroll
            for (int c = 0; c < 4; c++) acc[i][j][c] = 0.0f;

    load_stage(0);
    store_stage(0);

    for (int t = 0; t < T; t++) {
        __syncthreads();
        if (t + 1 < T) load_stage(t + 1);
        {
            const char* Ah = bufs[t & 1];
            const char* Al = Ah + TILE_BYTES;
            const char* Bh = Ah + 2 * TILE_BYTES;
            const char* Bl = Ah + 3 * TILE_BYTES;
#pragma unroll
            for (int kk = 0; kk < 2; kk++) {
                const int cb = kk * 32 + tq * 4;   // byte col offset of frag
                unsigned bh[4][2], bl[4][2];
#pragma unroll
                for (int nt = 0; nt < 4; nt++) {
                    unsigned roff = (nw * 32 + nt * 8 + g) * (SROW * 2) + cb;
                    bh[nt][0] = *(const unsigned*)(Bh + roff);
                    bh[nt][1] = *(const unsigned*)(Bh + roff + 16);
                    bl[nt][0] = *(const unsigned*)(Bl + roff);
                    bl[nt][1] = *(const unsigned*)(Bl + roff + 16);
                }
#pragma unroll
                for (int mt = 0; mt < 4; mt++) {
                    unsigned r0 = (mw * 64 + mt * 16 + g) * (SROW * 2) + cb;
                    unsigned ah[4], al[4];
                    ah[0] = *(const unsigned*)(Ah + r0);
                    ah[1] = *(const unsigned*)(Ah + r0 + 8 * (SROW * 2));
                    ah[2] = *(const unsigned*)(Ah + r0 + 16);
                    ah[3] = *(const unsigned*)(Ah + r0 + 8 * (SROW * 2) + 16);
                    al[0] = *(const unsigned*)(Al + r0);
                    al[1] = *(const unsigned*)(Al + r0 + 8 * (SROW * 2));
                    al[2] = *(const unsigned*)(Al + r0 + 16);
                    al[3] = *(const unsigned*)(Al + r0 + 8 * (SROW * 2) + 16);
#pragma unroll
                    for (int nt = 0; nt < 4; nt++) {
                        mma_bf16(acc[mt][nt], ah, bh[nt]);
                        mma_bf16(acc[mt][nt], ah, bl[nt]);
                        mma_bf16(acc[mt][nt], al, bh[nt]);
                    }
                }
            }
        }
        if (t + 1 < T) store_stage((t + 1) & 1);
    }

    // ---------------- epilogue ----------------
    if constexpr (MODE == 3) {
        __syncthreads();                      // smem free for C staging
        float* Cs = (float*)ds;               // [128][132]
#pragma unroll
        for (int mt = 0; mt < 4; mt++) {
#pragma unroll
            for (int nt = 0; nt < 4; nt++) {
                int row = mw * 64 + mt * 16 + g;
                int col = nw * 32 + nt * 8 + 2 * tq;
                Cs[(col) * 132 + row]           = acc[mt][nt][0];
                Cs[(col + 1) * 132 + row]       = acc[mt][nt][1];
                Cs[(col) * 132 + row + 8]       = acc[mt][nt][2];
                Cs[(col + 1) * 132 + row + 8]   = acc[mt][nt][3];
            }
        }
        __syncthreads();
        int bb = m0 >> 10;
        int hwb = m0 & 1023;
        size_t obase = ((size_t)bb << 20) + hwb;
#pragma unroll
        for (int i = 0; i < 64; i++) {
            int idx = i * 256 + tid;
            int nl = idx >> 7;
            int ml = idx & 127;
            int n = n0 + nl;
            float v = fmaf(Cs[nl * 132 + ml], g_s3[n], g_t3[n]);
            size_t addr = obase + ((size_t)n << 10) + ml;
            v += Xres[addr];
            Out[addr] = fmaxf(v, 0.0f);
        }
    } else {
        float* dst;
        if constexpr (MODE == 1)
            dst = g_h + ((size_t)((b_img << 10) + hw0)) * 256;
        else
            dst = g_h2 + (size_t)m0 * 256;
        const float* sc = (MODE == 1) ? g_s1 : g_s2;
        const float* tc = (MODE == 1) ? g_t1 : g_t2;
#pragma unroll
        for (int mt = 0; mt < 4; mt++) {
#pragma unroll
            for (int nt = 0; nt < 4; nt++) {
                int row = mw * 64 + mt * 16 + g;
                int col = n0 + nw * 32 + nt * 8 + 2 * tq;
                float s0 = sc[col], t0 = tc[col];
                float s1 = sc[col + 1], t1 = tc[col + 1];
                float2 v0, v1;
                v0.x = fmaxf(fmaf(acc[mt][nt][0], s0, t0), 0.0f);
                v0.y = fmaxf(fmaf(acc[mt][nt][1], s1, t1), 0.0f);
                v1.x = fmaxf(fmaf(acc[mt][nt][2], s0, t0), 0.0f);
                v1.y = fmaxf(fmaf(acc[mt][nt][3], s1, t1), 0.0f);
                *(float2*)(dst + (size_t)row * 256 + col) = v0;
                *(float2*)(dst + (size_t)(row + 8) * 256 + col) = v1;
            }
        }
    }
}

// ------------------------- offset conv (3x3, 256 -> 18) -------------------------
__global__ void offconv_kernel(const float* __restrict__ off_b) {
    __shared__ float wS[18 * 256];
    const int b = blockIdx.x >> 5;
    const int y = blockIdx.x & 31;
    const int warp = threadIdx.x >> 5;
    const int lane = threadIdx.x & 31;
    const int xa0 = warp * 2, xb0 = warp * 2 + 1;
    const float* hb = g_h + (size_t)b * (HW * PDIM);

    float acc0[18], acc1[18];
#pragma unroll
    for (int j = 0; j < 18; j++) { acc0[j] = 0.0f; acc1[j] = 0.0f; }

    for (int tap = 0; tap < 9; tap++) {
        __syncthreads();
        for (int i = threadIdx.x; i < 1152; i += 512)
            ((float4*)wS)[i] = ((const float4*)(g_offw + tap * 4608))[i];
        __syncthreads();
        int yy = y + tap / 3 - 1;
        if (yy < 0 || yy > 31) continue;
        int dx = tap % 3 - 1;
        int xa = xa0 + dx, xb = xb0 + dx;
        const float* rowp = hb + yy * (32 * PDIM);
#pragma unroll
        for (int half = 0; half < 2; half++) {
            int p = lane * 4 + half * 128;
            float4 ha = make_float4(0, 0, 0, 0), hbv = make_float4(0, 0, 0, 0);
            if (xa >= 0 && xa <= 31) ha  = *(const float4*)(rowp + xa * PDIM + p);
            if (xb >= 0 && xb <= 31) hbv = *(const float4*)(rowp + xb * PDIM + p);
#pragma unroll
            for (int j = 0; j < 18; j++) {
                float4 wv = *(const float4*)(wS + j * 256 + p);
                acc0[j] += ha.x * wv.x + ha.y * wv.y + ha.z * wv.z + ha.w * wv.w;
                acc1[j] += hbv.x * wv.x + hbv.y * wv.y + hbv.z * wv.z + hbv.w * wv.w;
            }
        }
    }
    for (int j = 0; j < 18; j++) {
        float r0 = acc0[j], r1 = acc1[j];
        for (int o = 16; o > 0; o >>= 1) {
            r0 += __shfl_xor_sync(0xffffffffu, r0, o);
            r1 += __shfl_xor_sync(0xffffffffu, r1, o);
        }
        if (lane == 0) {
            float bb = off_b[j];
            float* dst = g_off + ((b * 18 + j) * 32 + y) * 32;
            dst[xa0] = r0 + bb;
            dst[xb0] = r1 + bb;
        }
    }
}

// ------------------------- bilinear sampler -------------------------
__global__ void sampler_kernel() {
    int gi = blockIdx.x * 8 + (threadIdx.x >> 5);
    int lane = threadIdx.x & 31;
    int k = gi % 9;
    int t = gi / 9;
    int hw = t & 1023;
    int b = t >> 10;
    int y = hw >> 5, xx = hw & 31;

    const float* offp = g_off + b * (18 * HW) + (2 * k) * HW + hw;
    float oy = offp[0];
    float ox = offp[HW];
    float py = (float)(y + k / 3 - 1) + oy;
    float px = (float)(xx + k % 3 - 1) + ox;
    float y0f = floorf(py), x0f = floorf(px);
    float wy = py - y0f, wx = px - x0f;
    int y0 = (int)y0f, x0 = (int)x0f;
    int y1 = y0 + 1, x1 = x0 + 1;
    float vy0 = (y0 >= 0 && y0 <= 31) ? 1.0f : 0.0f;
    float vy1 = (y1 >= 0 && y1 <= 31) ? 1.0f : 0.0f;
    float vx0 = (x0 >= 0 && x0 <= 31) ? 1.0f : 0.0f;
    float vx1 = (x1 >= 0 && x1 <= 31) ? 1.0f : 0.0f;
    float w00 = (1.0f - wy) * (1.0f - wx) * vy0 * vx0;
    float w01 = (1.0f - wy) * wx * vy0 * vx1;
    float w10 = wy * (1.0f - wx) * vy1 * vx0;
    float w11 = wy * wx * vy1 * vx1;
    int y0c = min(max(y0, 0), 31), y1c = min(max(y1, 0), 31);
    int x0c = min(max(x0, 0), 31), x1c = min(max(x1, 0), 31);

    const float* base = g_h + (size_t)b * (HW * PDIM);
    const float* p00 = base + (y0c * 32 + x0c) * PDIM;
    const float* p01 = base + (y0c * 32 + x1c) * PDIM;
    const float* p10 = base + (y1c * 32 + x0c) * PDIM;
    const float* p11 = base + (y1c * 32 + x1c) * PDIM;
    float* dst = g_S + ((size_t)t * 9 + k) * PDIM;

#pragma unroll
    for (int half = 0; half < 2; half++) {
        int c = lane * 4 + half * 128;
        float4 a = *(const float4*)(p00 + c);
        float4 bq = *(const float4*)(p01 + c);
        float4 cq = *(const float4*)(p10 + c);
        float4 dq = *(const float4*)(p11 + c);
        float4 r;
        r.x = w00 * a.x + w01 * bq.x + w10 * cq.x + w11 * dq.x;
        r.y = w00 * a.y + w01 * bq.y + w10 * cq.y + w11 * dq.y;
        r.z = w00 * a.z + w01 * bq.z + w10 * cq.z + w11 * dq.z;
        r.w = w00 * a.w + w01 * bq.w + w10 * cq.w + w11 * dq.w;
        *(float4*)(dst + c) = r;
    }
}

// ------------------------- launcher -------------------------
extern "C" void kernel_launch(void* const* d_in, const int* in_sizes, int n_in,
                              void* d_out, int out_size) {
    const float* x     = (const float*)d_in[0];
    const float* w1    = (const float*)d_in[1];
    const float* bn1g  = (const float*)d_in[2];
    const float* bn1b  = (const float*)d_in[3];
    const float* bn1m  = (const float*)d_in[4];
    const float* bn1v  = (const float*)d_in[5];
    const float* off_w = (const float*)d_in[6];
    const float* off_b = (const float*)d_in[7];
    const float* w2    = (const float*)d_in[8];
    const float* bn2g  = (const float*)d_in[9];
    const float* bn2b  = (const float*)d_in[10];
    const float* bn2m  = (const float*)d_in[11];
    const float* bn2v  = (const float*)d_in[12];
    const float* w3    = (const float*)d_in[13];
    const float* bn3g  = (const float*)d_in[14];
    const float* bn3b  = (const float*)d_in[15];
    const float* bn3m  = (const float*)d_in[16];
    const float* bn3v  = (const float*)d_in[17];
    float* out = (float*)d_out;

    cudaFuncSetAttribute(tc_gemm<1>, cudaFuncAttributeMaxDynamicSharedMemorySize, SMEM_TOTAL);
    cudaFuncSetAttribute(tc_gemm<2>, cudaFuncAttributeMaxDynamicSharedMemorySize, SMEM_TOTAL);
    cudaFuncSetAttribute(tc_gemm<3>, cudaFuncAttributeMaxDynamicSharedMemorySize, SMEM_TOTAL);

    bnprep<<<4, 256>>>(bn1g, bn1b, bn1m, bn1v, bn2g, bn2b, bn2m, bn2v,
                       bn3g, bn3b, bn3m, bn3v);
    pack_offw<<<162, 256>>>(off_w);
    pack_w2<<<2304, 256>>>(w2);
    tc_gemm<1><<<dim3(128, 2), 256, SMEM_TOTAL>>>(x, w1, nullptr, nullptr);
    offconv_kernel<<<512, 512>>>(off_b);
    sampler_kernel<<<18432, 256>>>();
    tc_gemm<2><<<dim3(128, 2), 256, SMEM_TOTAL>>>(nullptr, nullptr, nullptr, nullptr);
    tc_gemm<3><<<dim3(128, 8), 256, SMEM_TOTAL>>>(nullptr, w3, x, out);
}

// round 4
// speedup vs baseline: 1.3540x; 1.2157x over previous
#include <cuda_runtime.h>
#include <cuda_bf16.h>

// ---------------------------------------------------------------------------
// DeformableBottleneck: B=16, Cin=O=1024, H=W=32, P=256.
// All GEMMs: mma.sync m16n8k16 bf16, bf16x3 compensation (AhBh+AhBl+AlBh).
// Operands pre-split to bf16 hi/lo in gmem; GEMM = cp.async 4-stage pipeline
// + ldmatrix fragments. CTA tile 128x128, K-tile 32, 8 warps (2m x 4n).
// ---------------------------------------------------------------------------

#define HW 1024
#define CIN 1024
#define PDIM 256
#define ODIM 1024
#define BATCH 16
#define KT 32

typedef unsigned uns;
typedef unsigned short us;

__device__ float g_h  [BATCH * HW * PDIM];          // h1 fp32 NHWC
__device__ us    g_h2h[BATCH * HW * PDIM];          // h2 hi/lo bf16
__device__ us    g_h2l[BATCH * HW * PDIM];
__device__ float g_off[BATCH * 18 * HW];
__device__ us    g_Sh [BATCH * HW * 9 * PDIM];      // sampled im2col hi/lo
__device__ us    g_Sl [BATCH * HW * 9 * PDIM];
__device__ us    g_xh [BATCH * CIN * HW];           // x split (k-major view)
__device__ us    g_xl [BATCH * CIN * HW];
__device__ us    g_w1h[PDIM * CIN],      g_w1l[PDIM * CIN];
__device__ us    g_w2h[PDIM * 9 * PDIM], g_w2l[PDIM * 9 * PDIM];
__device__ us    g_w3h[ODIM * PDIM],     g_w3l[ODIM * PDIM];
__device__ float g_offw[9 * 18 * PDIM];
__device__ float g_s1[PDIM], g_t1[PDIM];
__device__ float g_s2[PDIM], g_t2[PDIM];
__device__ float g_s3[ODIM], g_t3[ODIM];

// smem stage layout (bytes): Ah 0, Al 10240, Bh 20480, Bl 30720
#define OFF_AL 10240
#define OFF_BH 20480
#define OFF_BL 30720
#define STAGE  40960
#define NSTAGE 4
#define SMEM_TOTAL (NSTAGE * STAGE)

// ------------------------- PTX helpers -------------------------
__device__ __forceinline__ uns smem_u32(const void* p) {
    uns r;
    asm("{ .reg .u64 t; cvta.to.shared.u64 t, %1; cvt.u32.u64 %0, t; }"
        : "=r"(r) : "l"(p));
    return r;
}
__device__ __forceinline__ void cpa(uns dst, const void* src) {
    asm volatile("cp.async.cg.shared.global [%0], [%1], 16;" :: "r"(dst), "l"(src) : "memory");
}
__device__ __forceinline__ void cpa_commit() {
    asm volatile("cp.async.commit_group;" ::: "memory");
}
template <int N> __device__ __forceinline__ void cpa_wait() {
    asm volatile("cp.async.wait_group %0;" :: "n"(N) : "memory");
}
__device__ __forceinline__ void ldsm4(uns* r, uns a) {
    asm volatile("ldmatrix.sync.aligned.m8n8.x4.shared.b16 {%0,%1,%2,%3}, [%4];"
                 : "=r"(r[0]), "=r"(r[1]), "=r"(r[2]), "=r"(r[3]) : "r"(a));
}
__device__ __forceinline__ void ldsm4t(uns* r, uns a) {
    asm volatile("ldmatrix.sync.aligned.m8n8.x4.trans.shared.b16 {%0,%1,%2,%3}, [%4];"
                 : "=r"(r[0]), "=r"(r[1]), "=r"(r[2]), "=r"(r[3]) : "r"(a));
}
__device__ __forceinline__ void mma_bf16(float* d, const uns* a, const uns* b) {
    asm volatile(
        "mma.sync.aligned.m16n8k16.row.col.f32.bf16.bf16.f32 "
        "{%0,%1,%2,%3}, {%4,%5,%6,%7}, {%8,%9}, {%0,%1,%2,%3};"
        : "+f"(d[0]), "+f"(d[1]), "+f"(d[2]), "+f"(d[3])
        : "r"(a[0]), "r"(a[1]), "r"(a[2]), "r"(a[3]), "r"(b[0]), "r"(b[1]));
}
__device__ __forceinline__ void splitf(float x, us& h, us& l) {
    __nv_bfloat16 hb = __float2bfloat16(x);
    h = __bfloat16_as_ushort(hb);
    l = __bfloat16_as_ushort(__float2bfloat16(x - __bfloat162float(hb)));
}

// ------------------------- pack kernels -------------------------
__global__ void bnprep(const float* __restrict__ g1, const float* __restrict__ b1,
                       const float* __restrict__ m1, const float* __restrict__ v1,
                       const float* __restrict__ g2, const float* __restrict__ b2,
                       const float* __restrict__ m2, const float* __restrict__ v2,
                       const float* __restrict__ g3, const float* __restrict__ b3,
                       const float* __restrict__ m3, const float* __restrict__ v3) {
    int i = blockIdx.x * 256 + threadIdx.x;
    if (i < PDIM) {
        float s = g1[i] / sqrtf(v1[i] + 1e-5f);
        g_s1[i] = s; g_t1[i] = b1[i] - m1[i] * s;
        s = g2[i] / sqrtf(v2[i] + 1e-5f);
        g_s2[i] = s; g_t2[i] = b2[i] - m2[i] * s;
    }
    if (i < ODIM) {
        float s = g3[i] / sqrtf(v3[i] + 1e-5f);
        g_s3[i] = s; g_t3[i] = b3[i] - m3[i] * s;
    }
}

// WHICH: 0=x, 1=w1, 2=w3  (elementwise float4 -> 2x ushort4)
template <int WHICH>
__global__ void pack_split(const float* __restrict__ src) {
    int i = blockIdx.x * 256 + threadIdx.x;
    us* dh; us* dl;
    if constexpr (WHICH == 0)      { dh = g_xh;  dl = g_xl;  }
    else if constexpr (WHICH == 1) { dh = g_w1h; dl = g_w1l; }
    else                           { dh = g_w3h; dl = g_w3l; }
    float4 v = ((const float4*)src)[i];
    us h0, l0, h1, l1, h2, l2, h3, l3;
    splitf(v.x, h0, l0); splitf(v.y, h1, l1);
    splitf(v.z, h2, l2); splitf(v.w, h3, l3);
    ((ushort4*)dh)[i] = make_ushort4(h0, h1, h2, h3);
    ((ushort4*)dl)[i] = make_ushort4(l0, l1, l2, l3);
}

__global__ void pack_offw(const float* __restrict__ w) {
    int idx = blockIdx.x * 256 + threadIdx.x;
    int c = idx & 255;
    int j = (idx >> 8) % 18;
    int tap = idx / (256 * 18);
    g_offw[(tap * 18 + j) * 256 + c] = w[(j * 256 + c) * 9 + tap];
}
// w2 [o][c][tap] -> w2t hi/lo [o][tap*256+c]
__global__ void pack_w2(const float* __restrict__ w) {
    int idx = blockIdx.x * 256 + threadIdx.x;   // < 256*2304
    int o = idx / 2304;
    int r = idx % 2304;
    int k = r >> 8;
    int c = r & 255;
    us h, l;
    splitf(w[(o * 256 + c) * 9 + k], h, l);
    g_w2h[idx] = h;
    g_w2l[idx] = l;
}

// ------------------------- tensor-core GEMM -------------------------
// MODE 1: A = x split (k-major [c][hw] per batch), B = w1 -> g_h (+bn1+relu)
// MODE 2: A = S split [m][2304], B = w2t -> g_h2 hi/lo (+bn2+relu)
// MODE 3: A = h2 split [m][256], B = w3  -> OUT NCHW (+bn3+res+relu)
template <int MODE>
__global__ void __launch_bounds__(256) tc_gemm(const float* __restrict__ Xres,
                                               float* __restrict__ Out) {
    extern __shared__ char ds[];
    constexpr int Ktot = (MODE == 1) ? 1024 : (MODE == 2) ? 2304 : 256;
    constexpr int T = Ktot / KT;

    const int tid = threadIdx.x;
    const int lane = tid & 31;
    const int wid = tid >> 5;
    const int g = lane >> 2;
    const int tq = lane & 3;
    const int mw = wid & 1;
    const int nw = wid >> 1;
    const int n0 = blockIdx.y * 128;

    const us *Ah_g, *Al_g, *Bh_g, *Bl_g;
    int m0 = 0, b_img = 0, hw0 = 0;
    if constexpr (MODE == 1) {
        b_img = blockIdx.x >> 3;
        hw0 = (blockIdx.x & 7) << 7;
        Ah_g = g_xh + (size_t)b_img * (CIN * HW);
        Al_g = g_xl + (size_t)b_img * (CIN * HW);
        Bh_g = g_w1h + (size_t)n0 * Ktot;
        Bl_g = g_w1l + (size_t)n0 * Ktot;
    } else if constexpr (MODE == 2) {
        m0 = blockIdx.x * 128;
        Ah_g = g_Sh; Al_g = g_Sl;
        Bh_g = g_w2h + (size_t)n0 * Ktot;
        Bl_g = g_w2l + (size_t)n0 * Ktot;
    } else {
        m0 = blockIdx.x * 128;
        Ah_g = g_h2h; Al_g = g_h2l;
        Bh_g = g_w3h + (size_t)n0 * Ktot;
        Bl_g = g_w3l + (size_t)n0 * Ktot;
    }

    const uns sb = smem_u32(ds);

    auto issue = [&](int t) {
        const int k0 = t * KT;
        const uns st = sb + (t & 3) * STAGE;
        // B: 128 rows x 32k, 512 16B chunks per array
#pragma unroll
        for (int r = 0; r < 2; r++) {
            int i = tid + 256 * r;
            int row = i >> 2, c = i & 3;
            const us* sh = Bh_g + (size_t)row * Ktot + k0 + c * 8;
            const us* sl = Bl_g + (size_t)row * Ktot + k0 + c * 8;
            uns d = st + OFF_BH + row * 80 + c * 16;
            cpa(d, sh);
            cpa(d + (OFF_BL - OFF_BH), sl);
        }
        if constexpr (MODE == 1) {
            // A: 32 k-rows x 128 m, stride 272B
#pragma unroll
            for (int r = 0; r < 2; r++) {
                int i = tid + 256 * r;
                int row = i >> 4, c = i & 15;
                const us* sh = Ah_g + (size_t)(k0 + row) * HW + hw0 + c * 8;
                const us* sl = Al_g + (size_t)(k0 + row) * HW + hw0 + c * 8;
                uns d = st + row * 272 + c * 16;
                cpa(d, sh);
                cpa(d + OFF_AL, sl);
            }
        } else {
            // A: 128 m-rows x 32 k, stride 80B
#pragma unroll
            for (int r = 0; r < 2; r++) {
                int i = tid + 256 * r;
                int row = i >> 2, c = i & 3;
                const us* sh = Ah_g + (size_t)(m0 + row) * Ktot + k0 + c * 8;
                const us* sl = Al_g + (size_t)(m0 + row) * Ktot + k0 + c * 8;
                uns d = st + row * 80 + c * 16;
                cpa(d, sh);
                cpa(d + OFF_AL, sl);
            }
        }
        cpa_commit();
    };

    float acc[4][4][4];
#pragma unroll
    for (int i = 0; i < 4; i++)
#pragma unroll
        for (int j = 0; j < 4; j++)
#pragma unroll
            for (int c = 0; c < 4; c++) acc[i][j][c] = 0.0f;

    // fragment address components
    const int aRow  = (lane & 7) + ((lane >> 3) & 1) * 8;   // non-trans A / B
    const int aColB = (lane >> 4) * 16;
    const int tRow  = (lane & 7) + ((lane >> 4) & 1) * 8;   // trans A (mode1)
    const int tColB = ((lane >> 3) & 1) * 16;

    issue(0); issue(1); issue(2);

    for (int t = 0; t < T; t++) {
        cpa_wait<2>();
        __syncthreads();
        if (t + 3 < T) issue(t + 3); else cpa_commit();
        const uns st = sb + (t & 3) * STAGE;
#pragma unroll
        for (int kk = 0; kk < 2; kk++) {
            uns bh[4][2], bl[4][2];
#pragma unroll
            for (int p = 0; p < 2; p++) {
                uns r4[4];
                uns addr = st + OFF_BH + (nw * 32 + p * 16 + aRow) * 80 + kk * 32 + aColB;
                ldsm4(r4, addr);
                bh[2 * p][0] = r4[0]; bh[2 * p + 1][0] = r4[1];
                bh[2 * p][1] = r4[2]; bh[2 * p + 1][1] = r4[3];
                ldsm4(r4, addr + (OFF_BL - OFF_BH));
                bl[2 * p][0] = r4[0]; bl[2 * p + 1][0] = r4[1];
                bl[2 * p][1] = r4[2]; bl[2 * p + 1][1] = r4[3];
            }
#pragma unroll
            for (int mt = 0; mt < 4; mt++) {
                uns ah[4], al[4];
                if constexpr (MODE == 1) {
                    uns addr = st + (kk * 16 + tRow) * 272 + (mw * 64 + mt * 16) * 2 + tColB;
                    ldsm4t(ah, addr);
                    ldsm4t(al, addr + OFF_AL);
                } else {
                    uns addr = st + (mw * 64 + mt * 16 + aRow) * 80 + kk * 32 + aColB;
                    ldsm4(ah, addr);
                    ldsm4(al, addr + OFF_AL);
                }
#pragma unroll
                for (int nt = 0; nt < 4; nt++) {
                    mma_bf16(acc[mt][nt], ah, bh[nt]);
                    mma_bf16(acc[mt][nt], ah, bl[nt]);
                    mma_bf16(acc[mt][nt], al, bh[nt]);
                }
            }
        }
    }

    // ---------------- epilogue ----------------
    if constexpr (MODE == 3) {
        __syncthreads();
        float* Cs = (float*)ds;   // [128 n][132]
#pragma unroll
        for (int mt = 0; mt < 4; mt++) {
#pragma unroll
            for (int nt = 0; nt < 4; nt++) {
                int row = mw * 64 + mt * 16 + g;
                int col = nw * 32 + nt * 8 + 2 * tq;
                Cs[(col)     * 132 + row]     = acc[mt][nt][0];
                Cs[(col + 1) * 132 + row]     = acc[mt][nt][1];
                Cs[(col)     * 132 + row + 8] = acc[mt][nt][2];
                Cs[(col + 1) * 132 + row + 8] = acc[mt][nt][3];
            }
        }
        __syncthreads();
        int bb = m0 >> 10;
        int hwb = m0 & 1023;
        size_t obase = ((size_t)bb << 20) + hwb;
#pragma unroll
        for (int i = 0; i < 64; i++) {
            int idx = i * 256 + tid;
            int nl = idx >> 7;
            int ml = idx & 127;
            int n = n0 + nl;
            float v = fmaf(Cs[nl * 132 + ml], g_s3[n], g_t3[n]);
            size_t addr = obase + ((size_t)n << 10) + ml;
            v += Xres[addr];
            Out[addr] = fmaxf(v, 0.0f);
        }
    } else if constexpr (MODE == 2) {
        us* dh = g_h2h + (size_t)m0 * 256;
        us* dl = g_h2l + (size_t)m0 * 256;
#pragma unroll
        for (int mt = 0; mt < 4; mt++) {
#pragma unroll
            for (int nt = 0; nt < 4; nt++) {
                int row = mw * 64 + mt * 16 + g;
                int col = n0 + nw * 32 + nt * 8 + 2 * tq;
                float v0 = fmaxf(fmaf(acc[mt][nt][0], g_s2[col], g_t2[col]), 0.0f);
                float v1 = fmaxf(fmaf(acc[mt][nt][1], g_s2[col + 1], g_t2[col + 1]), 0.0f);
                float v2 = fmaxf(fmaf(acc[mt][nt][2], g_s2[col], g_t2[col]), 0.0f);
                float v3 = fmaxf(fmaf(acc[mt][nt][3], g_s2[col + 1], g_t2[col + 1]), 0.0f);
                us h0, l0, h1, l1, h2, l2, h3, l3;
                splitf(v0, h0, l0); splitf(v1, h1, l1);
                splitf(v2, h2, l2); splitf(v3, h3, l3);
                *(uns*)(dh + (size_t)row * 256 + col) = (uns)h0 | ((uns)h1 << 16);
                *(uns*)(dl + (size_t)row * 256 + col) = (uns)l0 | ((uns)l1 << 16);
                *(uns*)(dh + (size_t)(row + 8) * 256 + col) = (uns)h2 | ((uns)h3 << 16);
                *(uns*)(dl + (size_t)(row + 8) * 256 + col) = (uns)l2 | ((uns)l3 << 16);
            }
        }
    } else {
        float* dst = g_h + ((size_t)((b_img << 10) + hw0)) * 256;
#pragma unroll
        for (int mt = 0; mt < 4; mt++) {
#pragma unroll
            for (int nt = 0; nt < 4; nt++) {
                int row = mw * 64 + mt * 16 + g;
                int col = n0 + nw * 32 + nt * 8 + 2 * tq;
                float s0 = g_s1[col], t0 = g_t1[col];
                float s1 = g_s1[col + 1], t1 = g_t1[col + 1];
                float2 v0, v1;
                v0.x = fmaxf(fmaf(acc[mt][nt][0], s0, t0), 0.0f);
                v0.y = fmaxf(fmaf(acc[mt][nt][1], s1, t1), 0.0f);
                v1.x = fmaxf(fmaf(acc[mt][nt][2], s0, t0), 0.0f);
                v1.y = fmaxf(fmaf(acc[mt][nt][3], s1, t1), 0.0f);
                *(float2*)(dst + (size_t)row * 256 + col) = v0;
                *(float2*)(dst + (size_t)(row + 8) * 256 + col) = v1;
            }
        }
    }
}

// ------------------------- offset conv (3x3, 256 -> 18) -------------------------
__global__ void offconv_kernel(const float* __restrict__ off_b) {
    __shared__ float wS[18 * 256];
    const int b = blockIdx.x >> 5;
    const int y = blockIdx.x & 31;
    const int warp = threadIdx.x >> 5;
    const int lane = threadIdx.x & 31;
    const int xa0 = warp * 2, xb0 = warp * 2 + 1;
    const float* hb = g_h + (size_t)b * (HW * PDIM);

    float acc0[18], acc1[18];
#pragma unroll
    for (int j = 0; j < 18; j++) { acc0[j] = 0.0f; acc1[j] = 0.0f; }

    for (int tap = 0; tap < 9; tap++) {
        __syncthreads();
        for (int i = threadIdx.x; i < 1152; i += 512)
            ((float4*)wS)[i] = ((const float4*)(g_offw + tap * 4608))[i];
        __syncthreads();
        int yy = y + tap / 3 - 1;
        if (yy < 0 || yy > 31) continue;
        int dx = tap % 3 - 1;
        int xa = xa0 + dx, xb = xb0 + dx;
        const float* rowp = hb + yy * (32 * PDIM);
#pragma unroll
        for (int half = 0; half < 2; half++) {
            int p = lane * 4 + half * 128;
            float4 ha = make_float4(0, 0, 0, 0), hbv = make_float4(0, 0, 0, 0);
            if (xa >= 0 && xa <= 31) ha  = *(const float4*)(rowp + xa * PDIM + p);
            if (xb >= 0 && xb <= 31) hbv = *(const float4*)(rowp + xb * PDIM + p);
#pragma unroll
            for (int j = 0; j < 18; j++) {
                float4 wv = *(const float4*)(wS + j * 256 + p);
                acc0[j] += ha.x * wv.x + ha.y * wv.y + ha.z * wv.z + ha.w * wv.w;
                acc1[j] += hbv.x * wv.x + hbv.y * wv.y + hbv.z * wv.z + hbv.w * wv.w;
            }
        }
    }
    for (int j = 0; j < 18; j++) {
        float r0 = acc0[j], r1 = acc1[j];
        for (int o = 16; o > 0; o >>= 1) {
            r0 += __shfl_xor_sync(0xffffffffu, r0, o);
            r1 += __shfl_xor_sync(0xffffffffu, r1, o);
        }
        if (lane == 0) {
            float bb = off_b[j];
            float* dst = g_off + ((b * 18 + j) * 32 + y) * 32;
            dst[xa0] = r0 + bb;
            dst[xb0] = r1 + bb;
        }
    }
}

// ------------------------- bilinear sampler (emits bf16 hi/lo) ----------------
__global__ void sampler_kernel() {
    int gi = blockIdx.x * 8 + (threadIdx.x >> 5);
    int lane = threadIdx.x & 31;
    int k = gi % 9;
    int t = gi / 9;
    int hw = t & 1023;
    int b = t >> 10;
    int y = hw >> 5, xx = hw & 31;

    const float* offp = g_off + b * (18 * HW) + (2 * k) * HW + hw;
    float oy = offp[0];
    float ox = offp[HW];
    float py = (float)(y + k / 3 - 1) + oy;
    float px = (float)(xx + k % 3 - 1) + ox;
    float y0f = floorf(py), x0f = floorf(px);
    float wy = py - y0f, wx = px - x0f;
    int y0 = (int)y0f, x0 = (int)x0f;
    int y1 = y0 + 1, x1 = x0 + 1;
    float vy0 = (y0 >= 0 && y0 <= 31) ? 1.0f : 0.0f;
    float vy1 = (y1 >= 0 && y1 <= 31) ? 1.0f : 0.0f;
    float vx0 = (x0 >= 0 && x0 <= 31) ? 1.0f : 0.0f;
    float vx1 = (x1 >= 0 && x1 <= 31) ? 1.0f : 0.0f;
    float w00 = (1.0f - wy) * (1.0f - wx) * vy0 * vx0;
    float w01 = (1.0f - wy) * wx * vy0 * vx1;
    float w10 = wy * (1.0f - wx) * vy1 * vx0;
    float w11 = wy * wx * vy1 * vx1;
    int y0c = min(max(y0, 0), 31), y1c = min(max(y1, 0), 31);
    int x0c = min(max(x0, 0), 31), x1c = min(max(x1, 0), 31);

    const float* base = g_h + (size_t)b * (HW * PDIM);
    const float* p00 = base + (y0c * 32 + x0c) * PDIM;
    const float* p01 = base + (y0c * 32 + x1c) * PDIM;
    const float* p10 = base + (y1c * 32 + x0c) * PDIM;
    const float* p11 = base + (y1c * 32 + x1c) * PDIM;
    size_t dbase = ((size_t)t * 9 + k) * PDIM;

#pragma unroll
    for (int half = 0; half < 2; half++) {
        int c = lane * 4 + half * 128;
        float4 a = *(const float4*)(p00 + c);
        float4 bq = *(const float4*)(p01 + c);
        float4 cq = *(const float4*)(p10 + c);
        float4 dq = *(const float4*)(p11 + c);
        float4 r;
        r.x = w00 * a.x + w01 * bq.x + w10 * cq.x + w11 * dq.x;
        r.y = w00 * a.y + w01 * bq.y + w10 * cq.y + w11 * dq.y;
        r.z = w00 * a.z + w01 * bq.z + w10 * cq.z + w11 * dq.z;
        r.w = w00 * a.w + w01 * bq.w + w10 * cq.w + w11 * dq.w;
        us h0, l0, h1, l1, h2, l2, h3, l3;
        splitf(r.x, h0, l0); splitf(r.y, h1, l1);
        splitf(r.z, h2, l2); splitf(r.w, h3, l3);
        *(ushort4*)(g_Sh + dbase + c) = make_ushort4(h0, h1, h2, h3);
        *(ushort4*)(g_Sl + dbase + c) = make_ushort4(l0, l1, l2, l3);
    }
}

// ------------------------- launcher -------------------------
extern "C" void kernel_launch(void* const* d_in, const int* in_sizes, int n_in,
                              void* d_out, int out_size) {
    const float* x     = (const float*)d_in[0];
    const float* w1    = (const float*)d_in[1];
    const float* bn1g  = (const float*)d_in[2];
    const float* bn1b  = (const float*)d_in[3];
    const float* bn1m  = (const float*)d_in[4];
    const float* bn1v  = (const float*)d_in[5];
    const float* off_w = (const float*)d_in[6];
    const float* off_b = (const float*)d_in[7];
    const float* w2    = (const float*)d_in[8];
    const float* bn2g  = (const float*)d_in[9];
    const float* bn2b  = (const float*)d_in[10];
    const float* bn2m  = (const float*)d_in[11];
    const float* bn2v  = (const float*)d_in[12];
    const float* w3    = (const float*)d_in[13];
    const float* bn3g  = (const float*)d_in[14];
    const float* bn3b  = (const float*)d_in[15];
    const float* bn3m  = (const float*)d_in[16];
    const float* bn3v  = (const float*)d_in[17];
    float* out = (float*)d_out;

    cudaFuncSetAttribute(tc_gemm<1>, cudaFuncAttributeMaxDynamicSharedMemorySize, SMEM_TOTAL);
    cudaFuncSetAttribute(tc_gemm<2>, cudaFuncAttributeMaxDynamicSharedMemorySize, SMEM_TOTAL);
    cudaFuncSetAttribute(tc_gemm<3>, cudaFuncAttributeMaxDynamicSharedMemorySize, SMEM_TOTAL);

    bnprep<<<4, 256>>>(bn1g, bn1b, bn1m, bn1v, bn2g, bn2b, bn2m, bn2v,
                       bn3g, bn3b, bn3m, bn3v);
    pack_split<0><<<16384, 256>>>(x);     // x -> g_xh/g_xl
    pack_split<1><<<256, 256>>>(w1);      // w1
    pack_split<2><<<256, 256>>>(w3);      // w3
    pack_offw<<<162, 256>>>(off_w);
    pack_w2<<<2304, 256>>>(w2);
    tc_gemm<1><<<dim3(128, 2), 256, SMEM_TOTAL>>>(nullptr, nullptr);
    offconv_kernel<<<512, 512>>>(off_b);
    sampler_kernel<<<18432, 256>>>();
    tc_gemm<2><<<dim3(128, 2), 256, SMEM_TOTAL>>>(nullptr, nullptr);
    tc_gemm<3><<<dim3(128, 8), 256, SMEM_TOTAL>>>(x, out);
}

// round 5
// speedup vs baseline: 1.5571x; 1.1501x over previous
#include <cuda_runtime.h>
#include <cuda_bf16.h>

// ---------------------------------------------------------------------------
// DeformableBottleneck: B=16, Cin=O=1024, H=W=32, P=256.
// GEMMs: mma.sync m16n8k16 bf16, bf16x3 compensation (AhBh+AhBl+AlBh).
// 512 threads/CTA, 16 warps (4m x 4n), warp tile 32x32, cp.async 4-stage,
// ldmatrix fragments. h kept as bf16 hi/lo limbs (exact split of fp32).
// ---------------------------------------------------------------------------

#define HW 1024
#define CIN 1024
#define PDIM 256
#define ODIM 1024
#define BATCH 16
#define KT 32

typedef unsigned uns;
typedef unsigned short us;

__device__ us    g_hh [BATCH * HW * PDIM];          // h1 limbs, NHWC
__device__ us    g_hl [BATCH * HW * PDIM];
__device__ us    g_h2h[BATCH * HW * PDIM];          // h2 limbs
__device__ us    g_h2l[BATCH * HW * PDIM];
__device__ float g_off[BATCH * 18 * HW];
__device__ us    g_Sh [BATCH * HW * 9 * PDIM];      // sampled im2col limbs
__device__ us    g_Sl [BATCH * HW * 9 * PDIM];
__device__ us    g_xh [BATCH * CIN * HW];           // x limbs (k-major view)
__device__ us    g_xl [BATCH * CIN * HW];
__device__ us    g_w1h[PDIM * CIN],      g_w1l[PDIM * CIN];
__device__ us    g_w2h[PDIM * 9 * PDIM], g_w2l[PDIM * 9 * PDIM];
__device__ us    g_w3h[ODIM * PDIM],     g_w3l[ODIM * PDIM];
__device__ float g_offw[9 * 18 * PDIM];
__device__ float g_s1[PDIM], g_t1[PDIM];
__device__ float g_s2[PDIM], g_t2[PDIM];
__device__ float g_s3[ODIM], g_t3[ODIM];

// smem stage layout (bytes): Ah 0, Al 10240, Bh 20480, Bl 30720
#define OFF_AL 10240
#define OFF_BH 20480
#define OFF_BL 30720
#define STAGE  40960
#define NSTAGE 4
#define SMEM_TOTAL (NSTAGE * STAGE)

// ------------------------- PTX helpers -------------------------
__device__ __forceinline__ uns smem_u32(const void* p) {
    uns r;
    asm("{ .reg .u64 t; cvta.to.shared.u64 t, %1; cvt.u32.u64 %0, t; }"
        : "=r"(r) : "l"(p));
    return r;
}
__device__ __forceinline__ void cpa(uns dst, const void* src) {
    asm volatile("cp.async.cg.shared.global [%0], [%1], 16;" :: "r"(dst), "l"(src) : "memory");
}
__device__ __forceinline__ void cpa_commit() {
    asm volatile("cp.async.commit_group;" ::: "memory");
}
template <int N> __device__ __forceinline__ void cpa_wait() {
    asm volatile("cp.async.wait_group %0;" :: "n"(N) : "memory");
}
__device__ __forceinline__ void ldsm4(uns* r, uns a) {
    asm volatile("ldmatrix.sync.aligned.m8n8.x4.shared.b16 {%0,%1,%2,%3}, [%4];"
                 : "=r"(r[0]), "=r"(r[1]), "=r"(r[2]), "=r"(r[3]) : "r"(a));
}
__device__ __forceinline__ void ldsm4t(uns* r, uns a) {
    asm volatile("ldmatrix.sync.aligned.m8n8.x4.trans.shared.b16 {%0,%1,%2,%3}, [%4];"
                 : "=r"(r[0]), "=r"(r[1]), "=r"(r[2]), "=r"(r[3]) : "r"(a));
}
__device__ __forceinline__ void mma_bf16(float* d, const uns* a, const uns* b) {
    asm volatile(
        "mma.sync.aligned.m16n8k16.row.col.f32.bf16.bf16.f32 "
        "{%0,%1,%2,%3}, {%4,%5,%6,%7}, {%8,%9}, {%0,%1,%2,%3};"
        : "+f"(d[0]), "+f"(d[1]), "+f"(d[2]), "+f"(d[3])
        : "r"(a[0]), "r"(a[1]), "r"(a[2]), "r"(a[3]), "r"(b[0]), "r"(b[1]));
}
__device__ __forceinline__ void splitf(float x, us& h, us& l) {
    __nv_bfloat16 hb = __float2bfloat16(x);
    h = __bfloat16_as_ushort(hb);
    l = __bfloat16_as_ushort(__float2bfloat16(x - __bfloat162float(hb)));
}
__device__ __forceinline__ float bf2f(us u) {
    return __uint_as_float(((uns)u) << 16);
}

// ------------------------- pack kernels -------------------------
__global__ void bnprep(const float* __restrict__ g1, const float* __restrict__ b1,
                       const float* __restrict__ m1, const float* __restrict__ v1,
                       const float* __restrict__ g2, const float* __restrict__ b2,
                       const float* __restrict__ m2, const float* __restrict__ v2,
                       const float* __restrict__ g3, const float* __restrict__ b3,
                       const float* __restrict__ m3, const float* __restrict__ v3) {
    int i = blockIdx.x * 256 + threadIdx.x;
    if (i < PDIM) {
        float s = g1[i] / sqrtf(v1[i] + 1e-5f);
        g_s1[i] = s; g_t1[i] = b1[i] - m1[i] * s;
        s = g2[i] / sqrtf(v2[i] + 1e-5f);
        g_s2[i] = s; g_t2[i] = b2[i] - m2[i] * s;
    }
    if (i < ODIM) {
        float s = g3[i] / sqrtf(v3[i] + 1e-5f);
        g_s3[i] = s; g_t3[i] = b3[i] - m3[i] * s;
    }
}

// WHICH: 0=x, 1=w1, 2=w3  (elementwise float4 -> 2x ushort4)
template <int WHICH>
__global__ void pack_split(const float* __restrict__ src) {
    int i = blockIdx.x * 256 + threadIdx.x;
    us* dh; us* dl;
    if constexpr (WHICH == 0)      { dh = g_xh;  dl = g_xl;  }
    else if constexpr (WHICH == 1) { dh = g_w1h; dl = g_w1l; }
    else                           { dh = g_w3h; dl = g_w3l; }
    float4 v = ((const float4*)src)[i];
    us h0, l0, h1, l1, h2, l2, h3, l3;
    splitf(v.x, h0, l0); splitf(v.y, h1, l1);
    splitf(v.z, h2, l2); splitf(v.w, h3, l3);
    ((ushort4*)dh)[i] = make_ushort4(h0, h1, h2, h3);
    ((ushort4*)dl)[i] = make_ushort4(l0, l1, l2, l3);
}

__global__ void pack_offw(const float* __restrict__ w) {
    int idx = blockIdx.x * 256 + threadIdx.x;
    int c = idx & 255;
    int j = (idx >> 8) % 18;
    int tap = idx / (256 * 18);
    g_offw[(tap * 18 + j) * 256 + c] = w[(j * 256 + c) * 9 + tap];
}
__global__ void pack_w2(const float* __restrict__ w) {
    int idx = blockIdx.x * 256 + threadIdx.x;   // < 256*2304
    int o = idx / 2304;
    int r = idx % 2304;
    int k = r >> 8;
    int c = r & 255;
    us h, l;
    splitf(w[(o * 256 + c) * 9 + k], h, l);
    g_w2h[idx] = h;
    g_w2l[idx] = l;
}

// ------------------------- tensor-core GEMM -------------------------
// MODE 1: A = x limbs (k-major [c][hw] per batch), B = w1 -> g_hh/g_hl (+bn1+relu)
// MODE 2: A = S limbs [m][2304], B = w2t -> g_h2h/g_h2l (+bn2+relu)
// MODE 3: A = h2 limbs [m][256], B = w3  -> OUT NCHW (+bn3+res+relu)
template <int MODE>
__global__ void __launch_bounds__(512) tc_gemm(const float* __restrict__ Xres,
                                               float* __restrict__ Out) {
    extern __shared__ char ds[];
    constexpr int Ktot = (MODE == 1) ? 1024 : (MODE == 2) ? 2304 : 256;
    constexpr int T = Ktot / KT;

    const int tid = threadIdx.x;
    const int lane = tid & 31;
    const int wid = tid >> 5;
    const int g = lane >> 2;
    const int tq = lane & 3;
    const int mw = wid & 3;          // 4 m groups of 32 rows
    const int nw = wid >> 2;         // 4 n groups of 32 cols
    const int n0 = blockIdx.y * 128;

    const us *Ah_g, *Al_g, *Bh_g, *Bl_g;
    int m0 = 0, b_img = 0, hw0 = 0;
    if constexpr (MODE == 1) {
        b_img = blockIdx.x >> 3;
        hw0 = (blockIdx.x & 7) << 7;
        Ah_g = g_xh + (size_t)b_img * (CIN * HW);
        Al_g = g_xl + (size_t)b_img * (CIN * HW);
        Bh_g = g_w1h + (size_t)n0 * Ktot;
        Bl_g = g_w1l + (size_t)n0 * Ktot;
    } else if constexpr (MODE == 2) {
        m0 = blockIdx.x * 128;
        Ah_g = g_Sh; Al_g = g_Sl;
        Bh_g = g_w2h + (size_t)n0 * Ktot;
        Bl_g = g_w2l + (size_t)n0 * Ktot;
    } else {
        m0 = blockIdx.x * 128;
        Ah_g = g_h2h; Al_g = g_h2l;
        Bh_g = g_w3h + (size_t)n0 * Ktot;
        Bl_g = g_w3l + (size_t)n0 * Ktot;
    }

    const uns sb = smem_u32(ds);

    auto issue = [&](int t) {
        const int k0 = t * KT;
        const uns st = sb + (t & 3) * STAGE;
        // B: 128 rows x 32k -> 512 16B chunks per limb; 1 per thread
        {
            int row = tid >> 2, c = tid & 3;
            const us* sh = Bh_g + (size_t)row * Ktot + k0 + c * 8;
            const us* sl = Bl_g + (size_t)row * Ktot + k0 + c * 8;
            uns d = st + OFF_BH + row * 80 + c * 16;
            cpa(d, sh);
            cpa(d + (OFF_BL - OFF_BH), sl);
        }
        if constexpr (MODE == 1) {
            int row = tid >> 4, c = tid & 15;     // 32 k-rows x 16 chunks
            const us* sh = Ah_g + (size_t)(k0 + row) * HW + hw0 + c * 8;
            const us* sl = Al_g + (size_t)(k0 + row) * HW + hw0 + c * 8;
            uns d = st + row * 272 + c * 16;
            cpa(d, sh);
            cpa(d + OFF_AL, sl);
        } else {
            int row = tid >> 2, c = tid & 3;      // 128 m-rows x 4 chunks
            const us* sh = Ah_g + (size_t)(m0 + row) * Ktot + k0 + c * 8;
            const us* sl = Al_g + (size_t)(m0 + row) * Ktot + k0 + c * 8;
            uns d = st + row * 80 + c * 16;
            cpa(d, sh);
            cpa(d + OFF_AL, sl);
        }
        cpa_commit();
    };

    float acc[2][4][4];
#pragma unroll
    for (int i = 0; i < 2; i++)
#pragma unroll
        for (int j = 0; j < 4; j++)
#pragma unroll
            for (int c = 0; c < 4; c++) acc[i][j][c] = 0.0f;

    const int aRow  = (lane & 7) + ((lane >> 3) & 1) * 8;   // non-trans A / B
    const int aColB = (lane >> 4) * 16;
    const int tRow  = (lane & 7) + ((lane >> 4) & 1) * 8;   // trans A (mode1)
    const int tColB = ((lane >> 3) & 1) * 16;

    issue(0); issue(1); issue(2);

    for (int t = 0; t < T; t++) {
        cpa_wait<2>();
        __syncthreads();
        if (t + 3 < T) issue(t + 3); else cpa_commit();
        const uns st = sb + (t & 3) * STAGE;
#pragma unroll
        for (int kk = 0; kk < 2; kk++) {
            uns bh[4][2], bl[4][2];
#pragma unroll
            for (int p = 0; p < 2; p++) {
                uns r4[4];
                uns addr = st + OFF_BH + (nw * 32 + p * 16 + aRow) * 80 + kk * 32 + aColB;
                ldsm4(r4, addr);
                bh[2 * p][0] = r4[0]; bh[2 * p + 1][0] = r4[1];
                bh[2 * p][1] = r4[2]; bh[2 * p + 1][1] = r4[3];
                ldsm4(r4, addr + (OFF_BL - OFF_BH));
                bl[2 * p][0] = r4[0]; bl[2 * p + 1][0] = r4[1];
                bl[2 * p][1] = r4[2]; bl[2 * p + 1][1] = r4[3];
            }
#pragma unroll
            for (int mt = 0; mt < 2; mt++) {
                uns ah[4], al[4];
                if constexpr (MODE == 1) {
                    uns addr = st + (kk * 16 + tRow) * 272 + (mw * 32 + mt * 16) * 2 + tColB;
                    ldsm4t(ah, addr);
                    ldsm4t(al, addr + OFF_AL);
                } else {
                    uns addr = st + (mw * 32 + mt * 16 + aRow) * 80 + kk * 32 + aColB;
                    ldsm4(ah, addr);
                    ldsm4(al, addr + OFF_AL);
                }
#pragma unroll
                for (int nt = 0; nt < 4; nt++) {
                    mma_bf16(acc[mt][nt], ah, bh[nt]);
                    mma_bf16(acc[mt][nt], ah, bl[nt]);
                    mma_bf16(acc[mt][nt], al, bh[nt]);
                }
            }
        }
    }

    // ---------------- epilogue ----------------
    if constexpr (MODE == 3) {
        __syncthreads();
        float* Cs = (float*)ds;   // [128 n][132]
#pragma unroll
        for (int mt = 0; mt < 2; mt++) {
#pragma unroll
            for (int nt = 0; nt < 4; nt++) {
                int row = mw * 32 + mt * 16 + g;
                int col = nw * 32 + nt * 8 + 2 * tq;
                Cs[(col)     * 132 + row]     = acc[mt][nt][0];
                Cs[(col + 1) * 132 + row]     = acc[mt][nt][1];
                Cs[(col)     * 132 + row + 8] = acc[mt][nt][2];
                Cs[(col + 1) * 132 + row + 8] = acc[mt][nt][3];
            }
        }
        __syncthreads();
        int bb = m0 >> 10;
        int hwb = m0 & 1023;
        size_t obase = ((size_t)bb << 20) + hwb;
#pragma unroll
        for (int i = 0; i < 32; i++) {
            int idx = i * 512 + tid;
            int nl = idx >> 7;
            int ml = idx & 127;
            int n = n0 + nl;
            float v = fmaf(Cs[nl * 132 + ml], g_s3[n], g_t3[n]);
            size_t addr = obase + ((size_t)n << 10) + ml;
            v += Xres[addr];
            Out[addr] = fmaxf(v, 0.0f);
        }
    } else {
        us *dh, *dl;
        const float *sc, *tc;
        if constexpr (MODE == 1) {
            size_t base = ((size_t)((b_img << 10) + hw0)) * 256;
            dh = g_hh + base; dl = g_hl + base;
            sc = g_s1; tc = g_t1;
        } else {
            dh = g_h2h + (size_t)m0 * 256;
            dl = g_h2l + (size_t)m0 * 256;
            sc = g_s2; tc = g_t2;
        }
#pragma unroll
        for (int mt = 0; mt < 2; mt++) {
#pragma unroll
            for (int nt = 0; nt < 4; nt++) {
                int row = mw * 32 + mt * 16 + g;
                int col = n0 + nw * 32 + nt * 8 + 2 * tq;
                float s0 = sc[col], t0 = tc[col];
                float s1 = sc[col + 1], t1 = tc[col + 1];
                float v0 = fmaxf(fmaf(acc[mt][nt][0], s0, t0), 0.0f);
                float v1 = fmaxf(fmaf(acc[mt][nt][1], s1, t1), 0.0f);
                float v2 = fmaxf(fmaf(acc[mt][nt][2], s0, t0), 0.0f);
                float v3 = fmaxf(fmaf(acc[mt][nt][3], s1, t1), 0.0f);
                us h0, l0, h1, l1, h2, l2, h3, l3;
                splitf(v0, h0, l0); splitf(v1, h1, l1);
                splitf(v2, h2, l2); splitf(v3, h3, l3);
                *(uns*)(dh + (size_t)row * 256 + col) = (uns)h0 | ((uns)h1 << 16);
                *(uns*)(dl + (size_t)row * 256 + col) = (uns)l0 | ((uns)l1 << 16);
                *(uns*)(dh + (size_t)(row + 8) * 256 + col) = (uns)h2 | ((uns)h3 << 16);
                *(uns*)(dl + (size_t)(row + 8) * 256 + col) = (uns)l2 | ((uns)l3 << 16);
            }
        }
    }
}

// ------------------------- offset conv (3x3, 256 -> 18) -------------------------
__global__ void offconv_kernel(const float* __restrict__ off_b) {
    __shared__ float wS[18 * 256];
    const int b = blockIdx.x >> 5;
    const int y = blockIdx.x & 31;
    const int warp = threadIdx.x >> 5;
    const int lane = threadIdx.x & 31;
    const int xa0 = warp * 2, xb0 = warp * 2 + 1;
    const us* hh = g_hh + (size_t)b * (HW * PDIM);
    const us* hl = g_hl + (size_t)b * (HW * PDIM);

    float acc0[18], acc1[18];
#pragma unroll
    for (int j = 0; j < 18; j++) { acc0[j] = 0.0f; acc1[j] = 0.0f; }

    for (int tap = 0; tap < 9; tap++) {
        __syncthreads();
        for (int i = threadIdx.x; i < 1152; i += 512)
            ((float4*)wS)[i] = ((const float4*)(g_offw + tap * 4608))[i];
        __syncthreads();
        int yy = y + tap / 3 - 1;
        if (yy < 0 || yy > 31) continue;
        int dx = tap % 3 - 1;
        int xa = xa0 + dx, xb = xb0 + dx;
        const int rowo = yy * (32 * PDIM);
#pragma unroll
        for (int half = 0; half < 2; half++) {
            int p = lane * 4 + half * 128;
            float4 ha = make_float4(0, 0, 0, 0), hbv = make_float4(0, 0, 0, 0);
            if (xa >= 0 && xa <= 31) {
                ushort4 h4 = *(const ushort4*)(hh + rowo + xa * PDIM + p);
                ushort4 l4 = *(const ushort4*)(hl + rowo + xa * PDIM + p);
                ha.x = bf2f(h4.x) + bf2f(l4.x); ha.y = bf2f(h4.y) + bf2f(l4.y);
                ha.z = bf2f(h4.z) + bf2f(l4.z); ha.w = bf2f(h4.w) + bf2f(l4.w);
            }
            if (xb >= 0 && xb <= 31) {
                ushort4 h4 = *(const ushort4*)(hh + rowo + xb * PDIM + p);
                ushort4 l4 = *(const ushort4*)(hl + rowo + xb * PDIM + p);
                hbv.x = bf2f(h4.x) + bf2f(l4.x); hbv.y = bf2f(h4.y) + bf2f(l4.y);
                hbv.z = bf2f(h4.z) + bf2f(l4.z); hbv.w = bf2f(h4.w) + bf2f(l4.w);
            }
#pragma unroll
            for (int j = 0; j < 18; j++) {
                float4 wv = *(const float4*)(wS + j * 256 + p);
                acc0[j] += ha.x * wv.x + ha.y * wv.y + ha.z * wv.z + ha.w * wv.w;
                acc1[j] += hbv.x * wv.x + hbv.y * wv.y + hbv.z * wv.z + hbv.w * wv.w;
            }
        }
    }
    for (int j = 0; j < 18; j++) {
        float r0 = acc0[j], r1 = acc1[j];
        for (int o = 16; o > 0; o >>= 1) {
            r0 += __shfl_xor_sync(0xffffffffu, r0, o);
            r1 += __shfl_xor_sync(0xffffffffu, r1, o);
        }
        if (lane == 0) {
            float bb = off_b[j];
            float* dst = g_off + ((b * 18 + j) * 32 + y) * 32;
            dst[xa0] = r0 + bb;
            dst[xb0] = r1 + bb;
        }
    }
}

// ------------------------- bilinear sampler -------------------------
// warp per (b, hw, tap); lane covers 8 channels; h limbs summed in fp32.
__global__ void sampler_kernel() {
    int gi = blockIdx.x * 8 + (threadIdx.x >> 5);
    int lane = threadIdx.x & 31;
    int k = gi % 9;
    int t = gi / 9;
    int hw = t & 1023;
    int b = t >> 10;
    int y = hw >> 5, xx = hw & 31;

    const float* offp = g_off + b * (18 * HW) + (2 * k) * HW + hw;
    float oy = offp[0];
    float ox = offp[HW];
    float py = (float)(y + k / 3 - 1) + oy;
    float px = (float)(xx + k % 3 - 1) + ox;
    float y0f = floorf(py), x0f = floorf(px);
    float wy = py - y0f, wx = px - x0f;
    int y0 = (int)y0f, x0 = (int)x0f;
    int y1 = y0 + 1, x1 = x0 + 1;
    float vy0 = (y0 >= 0 && y0 <= 31) ? 1.0f : 0.0f;
    float vy1 = (y1 >= 0 && y1 <= 31) ? 1.0f : 0.0f;
    float vx0 = (x0 >= 0 && x0 <= 31) ? 1.0f : 0.0f;
    float vx1 = (x1 >= 0 && x1 <= 31) ? 1.0f : 0.0f;
    float wgt[4];
    wgt[0] = (1.0f - wy) * (1.0f - wx) * vy0 * vx0;
    wgt[1] = (1.0f - wy) * wx * vy0 * vx1;
    wgt[2] = wy * (1.0f - wx) * vy1 * vx0;
    wgt[3] = wy * wx * vy1 * vx1;
    int y0c = min(max(y0, 0), 31), y1c = min(max(y1, 0), 31);
    int x0c = min(max(x0, 0), 31), x1c = min(max(x1, 0), 31);

    const us* hh = g_hh + (size_t)b * (HW * PDIM);
    const us* hl = g_hl + (size_t)b * (HW * PDIM);
    int ci[4];
    ci[0] = (y0c * 32 + x0c) * PDIM;
    ci[1] = (y0c * 32 + x1c) * PDIM;
    ci[2] = (y1c * 32 + x0c) * PDIM;
    ci[3] = (y1c * 32 + x1c) * PDIM;

    const int c = lane * 8;
    uint4 Hq[4], Lq[4];
#pragma unroll
    for (int q = 0; q < 4; q++) {
        Hq[q] = *(const uint4*)(hh + ci[q] + c);
        Lq[q] = *(const uint4*)(hl + ci[q] + c);
    }

    uns oh[4], ol[4];
#pragma unroll
    for (int wi = 0; wi < 4; wi++) {
        float alo = 0.0f, ahi = 0.0f;
#pragma unroll
        for (int q = 0; q < 4; q++) {
            uns hu = ((const uns*)&Hq[q])[wi];
            uns lu = ((const uns*)&Lq[q])[wi];
            float vlo = __uint_as_float(hu << 16) + __uint_as_float(lu << 16);
            float vhi = __uint_as_float(hu & 0xffff0000u) + __uint_as_float(lu & 0xffff0000u);
            alo = fmaf(wgt[q], vlo, alo);
            ahi = fmaf(wgt[q], vhi, ahi);
        }
        us sh, sl, th, tl;
        splitf(alo, sh, sl);
        splitf(ahi, th, tl);
        oh[wi] = (uns)sh | ((uns)th << 16);
        ol[wi] = (uns)sl | ((uns)tl << 16);
    }
    size_t dbase = ((size_t)t * 9 + k) * PDIM + c;
    *(uint4*)(g_Sh + dbase) = make_uint4(oh[0], oh[1], oh[2], oh[3]);
    *(uint4*)(g_Sl + dbase) = make_uint4(ol[0], ol[1], ol[2], ol[3]);
}

// ------------------------- launcher -------------------------
extern "C" void kernel_launch(void* const* d_in, const int* in_sizes, int n_in,
                              void* d_out, int out_size) {
    const float* x     = (const float*)d_in[0];
    const float* w1    = (const float*)d_in[1];
    const float* bn1g  = (const float*)d_in[2];
    const float* bn1b  = (const float*)d_in[3];
    const float* bn1m  = (const float*)d_in[4];
    const float* bn1v  = (const float*)d_in[5];
    const float* off_w = (const float*)d_in[6];
    const float* off_b = (const float*)d_in[7];
    const float* w2    = (const float*)d_in[8];
    const float* bn2g  = (const float*)d_in[9];
    const float* bn2b  = (const float*)d_in[10];
    const float* bn2m  = (const float*)d_in[11];
    const float* bn2v  = (const float*)d_in[12];
    const float* w3    = (const float*)d_in[13];
    const float* bn3g  = (const float*)d_in[14];
    const float* bn3b  = (const float*)d_in[15];
    const float* bn3m  = (const float*)d_in[16];
    const float* bn3v  = (const float*)d_in[17];
    float* out = (float*)d_out;

    cudaFuncSetAttribute(tc_gemm<1>, cudaFuncAttributeMaxDynamicSharedMemorySize, SMEM_TOTAL);
    cudaFuncSetAttribute(tc_gemm<2>, cudaFuncAttributeMaxDynamicSharedMemorySize, SMEM_TOTAL);
    cudaFuncSetAttribute(tc_gemm<3>, cudaFuncAttributeMaxDynamicSharedMemorySize, SMEM_TOTAL);

    bnprep<<<4, 256>>>(bn1g, bn1b, bn1m, bn1v, bn2g, bn2b, bn2m, bn2v,
                       bn3g, bn3b, bn3m, bn3v);
    pack_split<0><<<16384, 256>>>(x);
    pack_split<1><<<256, 256>>>(w1);
    pack_split<2><<<256, 256>>>(w3);
    pack_offw<<<162, 256>>>(off_w);
    pack_w2<<<2304, 256>>>(w2);
    tc_gemm<1><<<dim3(128, 2), 512, SMEM_TOTAL>>>(nullptr, nullptr);
    offconv_kernel<<<512, 512>>>(off_b);
    sampler_kernel<<<18432, 256>>>();
    tc_gemm<2><<<dim3(128, 2), 512, SMEM_TOTAL>>>(nullptr, nullptr);
    tc_gemm<3><<<dim3(128, 8), 512, SMEM_TOTAL>>>(x, out);
}